// round 2
// baseline (speedup 1.0000x reference)
#include <cuda_runtime.h>
#include <cuda_bf16.h>
#include <math.h>

// Problem constants
#define Bq   2
#define Sq   2048
#define Dq   1024
#define Hq   16
#define HDq  64
#define Mq   (Bq*Sq)          // 4096 rows
#define SCALE_ATT 0.03125f    // sqrt(1/1024)

// ---------------- scratch (static device globals; no allocations) -------------
__device__ float g_qp [Mq*Dq];
__device__ float g_kp [Mq*Dq];
__device__ float g_vp [Mq*Dq];
__device__ float g_att[Mq*Dq];

// ---------------- GELU (exact, matches jax approximate=False) -----------------
__device__ __forceinline__ float gelu_exact(float x) {
    return 0.5f * x * (1.0f + erff(x * 0.70710678118654752f));
}

// ---------------- GEMM: C[m,n] = post( sum_k A[m,k]*W[n,k] + b[n] ) -----------
// A: [M,K] row-major, W: [N,K] row-major (X @ W^T). M=4096, N=K=1024.
// ROPE template flag: apply gelu then in-register RoPE rotation on column pairs.
#define BM 128
#define BN 128
#define BKk 16
#define TMm 8
#define TNn 8
#define NT  (Dq / BKk)   // 64 k-tiles

struct ProjArgs {
    const float* A[3];
    const float* W[3];
    const float* bias[3];
    float*       C[3];
};

template <bool FUSED3, bool ROPE>
__global__ __launch_bounds__(256)
void gemm_nt_bias_gelu(ProjArgs pa)
{
    __shared__ float As[2][BKk][BM];
    __shared__ float Bs[2][BKk][BN];

    const int z = FUSED3 ? blockIdx.z : 0;
    const float* __restrict__ A    = pa.A[z];
    const float* __restrict__ W    = pa.W[z];
    const float* __restrict__ bias = pa.bias[z];
    float* __restrict__ C          = pa.C[z];
    // z==2 is the V projection: no RoPE even in fused mode
    const bool do_rope = ROPE && (!FUSED3 || z < 2);

    const int tid = threadIdx.x;
    const int block_row = blockIdx.x * BM;
    const int block_col = blockIdx.y * BN;

    const int trow = (tid >> 4) * TMm;   // 0..120
    const int tcol = (tid & 15) * TNn;   // 0..120

    // per-thread load coords (2 rows of A tile + 2 rows of W tile, 4 k each)
    const int r0  = tid >> 2;            // 0..63
    const int r1  = r0 + 64;             // 64..127
    const int kc  = (tid & 3) * 4;       // 0,4,8,12

    float acc[TMm][TNn];
    #pragma unroll
    for (int i = 0; i < TMm; i++)
        #pragma unroll
        for (int j = 0; j < TNn; j++) acc[i][j] = 0.0f;

    float4 pa0, pa1, pw0, pw1;

    // prefetch tile 0
    {
        const float* Ab = A + (size_t)block_row * Dq + kc;
        const float* Wb = W + (size_t)block_col * Dq + kc;
        pa0 = *(const float4*)(Ab + (size_t)r0 * Dq);
        pa1 = *(const float4*)(Ab + (size_t)r1 * Dq);
        pw0 = *(const float4*)(Wb + (size_t)r0 * Dq);
        pw1 = *(const float4*)(Wb + (size_t)r1 * Dq);
    }
    // store tile 0 into buffer 0
    As[0][kc+0][r0] = pa0.x; As[0][kc+1][r0] = pa0.y; As[0][kc+2][r0] = pa0.z; As[0][kc+3][r0] = pa0.w;
    As[0][kc+0][r1] = pa1.x; As[0][kc+1][r1] = pa1.y; As[0][kc+2][r1] = pa1.z; As[0][kc+3][r1] = pa1.w;
    Bs[0][kc+0][r0] = pw0.x; Bs[0][kc+1][r0] = pw0.y; Bs[0][kc+2][r0] = pw0.z; Bs[0][kc+3][r0] = pw0.w;
    Bs[0][kc+0][r1] = pw1.x; Bs[0][kc+1][r1] = pw1.y; Bs[0][kc+2][r1] = pw1.z; Bs[0][kc+3][r1] = pw1.w;
    __syncthreads();

    for (int kt = 0; kt < NT; kt++) {
        const int cur = kt & 1;
        const int nxt = cur ^ 1;

        // issue global loads for next tile early
        if (kt + 1 < NT) {
            const int k0 = (kt + 1) * BKk;
            const float* Ab = A + (size_t)block_row * Dq + k0 + kc;
            const float* Wb = W + (size_t)block_col * Dq + k0 + kc;
            pa0 = *(const float4*)(Ab + (size_t)r0 * Dq);
            pa1 = *(const float4*)(Ab + (size_t)r1 * Dq);
            pw0 = *(const float4*)(Wb + (size_t)r0 * Dq);
            pw1 = *(const float4*)(Wb + (size_t)r1 * Dq);
        }

        // compute on current buffer
        #pragma unroll
        for (int kk = 0; kk < BKk; kk++) {
            float ar[TMm], br[TNn];
            #pragma unroll
            for (int i = 0; i < TMm; i += 4) {
                float4 t = *(const float4*)(&As[cur][kk][trow + i]);
                ar[i] = t.x; ar[i+1] = t.y; ar[i+2] = t.z; ar[i+3] = t.w;
            }
            #pragma unroll
            for (int j = 0; j < TNn; j += 4) {
                float4 t = *(const float4*)(&Bs[cur][kk][tcol + j]);
                br[j] = t.x; br[j+1] = t.y; br[j+2] = t.z; br[j+3] = t.w;
            }
            #pragma unroll
            for (int i = 0; i < TMm; i++)
                #pragma unroll
                for (int j = 0; j < TNn; j++)
                    acc[i][j] = fmaf(ar[i], br[j], acc[i][j]);
        }

        // store prefetched tile into next buffer
        if (kt + 1 < NT) {
            As[nxt][kc+0][r0] = pa0.x; As[nxt][kc+1][r0] = pa0.y; As[nxt][kc+2][r0] = pa0.z; As[nxt][kc+3][r0] = pa0.w;
            As[nxt][kc+0][r1] = pa1.x; As[nxt][kc+1][r1] = pa1.y; As[nxt][kc+2][r1] = pa1.z; As[nxt][kc+3][r1] = pa1.w;
            Bs[nxt][kc+0][r0] = pw0.x; Bs[nxt][kc+1][r0] = pw0.y; Bs[nxt][kc+2][r0] = pw0.z; Bs[nxt][kc+3][r0] = pw0.w;
            Bs[nxt][kc+0][r1] = pw1.x; Bs[nxt][kc+1][r1] = pw1.y; Bs[nxt][kc+2][r1] = pw1.z; Bs[nxt][kc+3][r1] = pw1.w;
            __syncthreads();
        }
    }

    // epilogue: bias + gelu (+ optional in-register RoPE on column pairs)
    const float LOG_BASE = 9.210340371976184f; // ln(10000)
    #pragma unroll
    for (int i = 0; i < TMm; i++) {
        const int row = block_row + trow + i;
        float* crow = C + (size_t)row * Dq + block_col + tcol;
        const float s_pos = (float)(row & (Sq - 1));
        #pragma unroll
        for (int j = 0; j < TNn; j += 4) {
            const int col = block_col + tcol + j;
            float v0 = gelu_exact(acc[i][j+0] + bias[col + 0]);
            float v1 = gelu_exact(acc[i][j+1] + bias[col + 1]);
            float v2 = gelu_exact(acc[i][j+2] + bias[col + 2]);
            float v3 = gelu_exact(acc[i][j+3] + bias[col + 3]);
            float4 o;
            if (do_rope) {
                // pair (col, col+1): hd = col & 63 (even), theta = 10000^(-hd/64)
                int hd0 = col & (HDq - 1);
                float th0 = __expf(-((float)hd0 / (float)HDq) * LOG_BASE);
                float sn0, cs0; sincosf(s_pos * th0, &sn0, &cs0);
                o.x = v0 * cs0 - v1 * sn0;
                o.y = v1 * cs0 + v0 * sn0;
                int hd2 = (col + 2) & (HDq - 1);
                float th2 = __expf(-((float)hd2 / (float)HDq) * LOG_BASE);
                float sn2, cs2; sincosf(s_pos * th2, &sn2, &cs2);
                o.z = v2 * cs2 - v3 * sn2;
                o.w = v3 * cs2 + v2 * sn2;
            } else {
                o.x = v0; o.y = v1; o.z = v2; o.w = v3;
            }
            *(float4*)(crow + j) = o;
        }
    }
}

// ---------------- Flash attention --------------------------------------------
// Groups n in [0,32): e = n>>4 (sequence parity), h = n&15 (head).
// Position p in [0,2048): b = p>>10, s = 2*(p&1023) + e.
// Element access: arr[(b*S+s)*D + h*64 + hd].
// One thread = one query row; TK=32 keys per smem tile.
#define TQ 128
#define TK 32

__global__ __launch_bounds__(TQ)
void attn_kernel()
{
    __shared__ float Ks[TK][HDq];
    __shared__ float Vs[TK][HDq];

    const int n = blockIdx.y;
    const int e = n >> 4;
    const int h = n & 15;

    const int p  = blockIdx.x * TQ + threadIdx.x;
    const int bq = p >> 10;
    const int sq = 2 * (p & 1023) + e;

    const float* qrow = g_qp + ((size_t)(bq * Sq + sq) * Dq + h * HDq);
    float q[HDq];
    #pragma unroll
    for (int d = 0; d < HDq; d += 4) {
        float4 t = *(const float4*)(qrow + d);
        q[d] = t.x; q[d+1] = t.y; q[d+2] = t.z; q[d+3] = t.w;
    }

    float o[HDq];
    #pragma unroll
    for (int d = 0; d < HDq; d++) o[d] = 0.0f;
    float mmax = -1e30f;
    float lsum = 0.0f;

    for (int kt = 0; kt < Sq; kt += TK) {
        // cooperative load of K,V tile: TK*HD = 2048 floats each = 512 float4; 4/thread
        #pragma unroll
        for (int l = 0; l < 4; l++) {
            int i = threadIdx.x + l * TQ;     // 0..511
            int j = i >> 4;                   // 0..31
            int d = (i & 15) * 4;             // 0..60
            int pk = kt + j;
            int bk = pk >> 10;
            int sk = 2 * (pk & 1023) + e;
            size_t off = (size_t)(bk * Sq + sk) * Dq + h * HDq + d;
            *(float4*)(&Ks[j][d]) = *(const float4*)(g_kp + off);
            *(float4*)(&Vs[j][d]) = *(const float4*)(g_vp + off);
        }
        __syncthreads();

        // scores for this tile
        float sc[TK];
        float tmax = -1e30f;
        #pragma unroll
        for (int j = 0; j < TK; j++) {
            float s = 0.0f;
            #pragma unroll
            for (int d = 0; d < HDq; d += 4) {
                float4 kv = *(const float4*)(&Ks[j][d]);
                s = fmaf(q[d+0], kv.x, s);
                s = fmaf(q[d+1], kv.y, s);
                s = fmaf(q[d+2], kv.z, s);
                s = fmaf(q[d+3], kv.w, s);
            }
            s *= SCALE_ATT;
            sc[j] = s;
            tmax = fmaxf(tmax, s);
        }

        // online softmax update
        float mnew = fmaxf(mmax, tmax);
        float corr = __expf(mmax - mnew);
        lsum *= corr;
        #pragma unroll
        for (int d = 0; d < HDq; d++) o[d] *= corr;

        #pragma unroll
        for (int j = 0; j < TK; j++) {
            float pj = __expf(sc[j] - mnew);
            lsum += pj;
            #pragma unroll
            for (int d = 0; d < HDq; d += 4) {
                float4 vv = *(const float4*)(&Vs[j][d]);
                o[d+0] = fmaf(pj, vv.x, o[d+0]);
                o[d+1] = fmaf(pj, vv.y, o[d+1]);
                o[d+2] = fmaf(pj, vv.z, o[d+2]);
                o[d+3] = fmaf(pj, vv.w, o[d+3]);
            }
        }
        mmax = mnew;
        __syncthreads();
    }

    float inv = 1.0f / lsum;
    float* orow = g_att + ((size_t)(bq * Sq + sq) * Dq + h * HDq);
    #pragma unroll
    for (int d = 0; d < HDq; d += 4) {
        float4 t;
        t.x = o[d+0] * inv; t.y = o[d+1] * inv;
        t.z = o[d+2] * inv; t.w = o[d+3] * inv;
        *(float4*)(orow + d) = t;
    }
}

// ---------------- launch ------------------------------------------------------
extern "C" void kernel_launch(void* const* d_in, const int* in_sizes, int n_in,
                              void* d_out, int out_size)
{
    const float* q  = (const float*)d_in[0];
    const float* k  = (const float*)d_in[1];
    const float* v  = (const float*)d_in[2];
    const float* Wq = (const float*)d_in[3];
    const float* bq = (const float*)d_in[4];
    const float* Wk = (const float*)d_in[5];
    const float* bk = (const float*)d_in[6];
    const float* Wv = (const float*)d_in[7];
    const float* bv = (const float*)d_in[8];
    const float* Wo = (const float*)d_in[9];
    const float* bo = (const float*)d_in[10];
    float* out = (float*)d_out;

    float *p_qp, *p_kp, *p_vp, *p_att;
    cudaGetSymbolAddress((void**)&p_qp,  g_qp);
    cudaGetSymbolAddress((void**)&p_kp,  g_kp);
    cudaGetSymbolAddress((void**)&p_vp,  g_vp);
    cudaGetSymbolAddress((void**)&p_att, g_att);

    // fused Q/K/V projections (+bias, gelu; RoPE fused for Q and K)
    ProjArgs pa;
    pa.A[0] = q;  pa.A[1] = k;  pa.A[2] = v;
    pa.W[0] = Wq; pa.W[1] = Wk; pa.W[2] = Wv;
    pa.bias[0] = bq; pa.bias[1] = bk; pa.bias[2] = bv;
    pa.C[0] = p_qp; pa.C[1] = p_kp; pa.C[2] = p_vp;

    dim3 pgrid(Mq / BM, Dq / BN, 3);   // (32, 8, 3)
    gemm_nt_bias_gelu<true, true><<<pgrid, 256>>>(pa);

    dim3 agrid(Sq / TQ, 32);           // (16, 32)
    attn_kernel<<<agrid, TQ>>>();

    // output projection (+bias, gelu)
    ProjArgs po;
    po.A[0] = p_att; po.W[0] = Wo; po.bias[0] = bo; po.C[0] = out;
    po.A[1] = po.A[2] = nullptr; po.W[1] = po.W[2] = nullptr;
    po.bias[1] = po.bias[2] = nullptr; po.C[1] = po.C[2] = nullptr;

    dim3 ogrid(Mq / BM, Dq / BN, 1);   // (32, 8)
    gemm_nt_bias_gelu<false, false><<<ogrid, 256>>>(po);
}

// round 7
// speedup vs baseline: 1.0765x; 1.0765x over previous
#include <cuda_runtime.h>
#include <cuda_bf16.h>
#include <math.h>

// Problem constants
#define Bq   2
#define Sq   2048
#define Dq   1024
#define Hq   16
#define HDq  64
#define Mq   (Bq*Sq)          // 4096 rows
#define SCALE_ATT 0.03125f    // sqrt(1/1024)

// ---------------- scratch (static device globals; no allocations) -------------
__device__ float g_qp [Mq*Dq];
__device__ float g_kp [Mq*Dq];
__device__ float g_vp [Mq*Dq];
__device__ float g_att[Mq*Dq];

// ---------------- GELU (exact, matches jax approximate=False) -----------------
__device__ __forceinline__ float gelu_exact(float x) {
    return 0.5f * x * (1.0f + erff(x * 0.70710678118654752f));
}

// ---------------- GEMM: C[m,n] = post( sum_k A[m,k]*W[n,k] + b[n] ) -----------
// A: [M,K] row-major, W: [N,K] row-major (X @ W^T). M=4096, N=K=1024.
#define BM 128
#define BN 128
#define BKk 16
#define TMm 8
#define TNn 8
#define NT  (Dq / BKk)   // 64 k-tiles

struct ProjArgs {
    const float* A[3];
    const float* W[3];
    const float* bias[3];
    float*       C[3];
};

template <bool FUSED3, bool ROPE>
__global__ __launch_bounds__(256)
void gemm_nt_bias_gelu(ProjArgs pa)
{
    __shared__ float As[2][BKk][BM];
    __shared__ float Bs[2][BKk][BN];

    const int z = FUSED3 ? blockIdx.z : 0;
    const float* __restrict__ A    = pa.A[z];
    const float* __restrict__ W    = pa.W[z];
    const float* __restrict__ bias = pa.bias[z];
    float* __restrict__ C          = pa.C[z];
    const bool do_rope = ROPE && (!FUSED3 || z < 2);

    const int tid = threadIdx.x;
    const int block_row = blockIdx.x * BM;
    const int block_col = blockIdx.y * BN;

    const int trow = (tid >> 4) * TMm;   // 0..120
    const int tcol = (tid & 15) * TNn;   // 0..120

    const int r0  = tid >> 2;            // 0..63
    const int r1  = r0 + 64;             // 64..127
    const int kc  = (tid & 3) * 4;       // 0,4,8,12

    float acc[TMm][TNn];
    #pragma unroll
    for (int i = 0; i < TMm; i++)
        #pragma unroll
        for (int j = 0; j < TNn; j++) acc[i][j] = 0.0f;

    float4 pa0, pa1, pw0, pw1;

    {
        const float* Ab = A + (size_t)block_row * Dq + kc;
        const float* Wb = W + (size_t)block_col * Dq + kc;
        pa0 = *(const float4*)(Ab + (size_t)r0 * Dq);
        pa1 = *(const float4*)(Ab + (size_t)r1 * Dq);
        pw0 = *(const float4*)(Wb + (size_t)r0 * Dq);
        pw1 = *(const float4*)(Wb + (size_t)r1 * Dq);
    }
    As[0][kc+0][r0] = pa0.x; As[0][kc+1][r0] = pa0.y; As[0][kc+2][r0] = pa0.z; As[0][kc+3][r0] = pa0.w;
    As[0][kc+0][r1] = pa1.x; As[0][kc+1][r1] = pa1.y; As[0][kc+2][r1] = pa1.z; As[0][kc+3][r1] = pa1.w;
    Bs[0][kc+0][r0] = pw0.x; Bs[0][kc+1][r0] = pw0.y; Bs[0][kc+2][r0] = pw0.z; Bs[0][kc+3][r0] = pw0.w;
    Bs[0][kc+0][r1] = pw1.x; Bs[0][kc+1][r1] = pw1.y; Bs[0][kc+2][r1] = pw1.z; Bs[0][kc+3][r1] = pw1.w;
    __syncthreads();

    for (int kt = 0; kt < NT; kt++) {
        const int cur = kt & 1;
        const int nxt = cur ^ 1;

        if (kt + 1 < NT) {
            const int k0 = (kt + 1) * BKk;
            const float* Ab = A + (size_t)block_row * Dq + k0 + kc;
            const float* Wb = W + (size_t)block_col * Dq + k0 + kc;
            pa0 = *(const float4*)(Ab + (size_t)r0 * Dq);
            pa1 = *(const float4*)(Ab + (size_t)r1 * Dq);
            pw0 = *(const float4*)(Wb + (size_t)r0 * Dq);
            pw1 = *(const float4*)(Wb + (size_t)r1 * Dq);
        }

        #pragma unroll
        for (int kk = 0; kk < BKk; kk++) {
            float ar[TMm], br[TNn];
            #pragma unroll
            for (int i = 0; i < TMm; i += 4) {
                float4 t = *(const float4*)(&As[cur][kk][trow + i]);
                ar[i] = t.x; ar[i+1] = t.y; ar[i+2] = t.z; ar[i+3] = t.w;
            }
            #pragma unroll
            for (int j = 0; j < TNn; j += 4) {
                float4 t = *(const float4*)(&Bs[cur][kk][tcol + j]);
                br[j] = t.x; br[j+1] = t.y; br[j+2] = t.z; br[j+3] = t.w;
            }
            #pragma unroll
            for (int i = 0; i < TMm; i++)
                #pragma unroll
                for (int j = 0; j < TNn; j++)
                    acc[i][j] = fmaf(ar[i], br[j], acc[i][j]);
        }

        if (kt + 1 < NT) {
            As[nxt][kc+0][r0] = pa0.x; As[nxt][kc+1][r0] = pa0.y; As[nxt][kc+2][r0] = pa0.z; As[nxt][kc+3][r0] = pa0.w;
            As[nxt][kc+0][r1] = pa1.x; As[nxt][kc+1][r1] = pa1.y; As[nxt][kc+2][r1] = pa1.z; As[nxt][kc+3][r1] = pa1.w;
            Bs[nxt][kc+0][r0] = pw0.x; Bs[nxt][kc+1][r0] = pw0.y; Bs[nxt][kc+2][r0] = pw0.z; Bs[nxt][kc+3][r0] = pw0.w;
            Bs[nxt][kc+0][r1] = pw1.x; Bs[nxt][kc+1][r1] = pw1.y; Bs[nxt][kc+2][r1] = pw1.z; Bs[nxt][kc+3][r1] = pw1.w;
            __syncthreads();
        }
    }

    const float LOG_BASE = 9.210340371976184f; // ln(10000)
    #pragma unroll
    for (int i = 0; i < TMm; i++) {
        const int row = block_row + trow + i;
        float* crow = C + (size_t)row * Dq + block_col + tcol;
        const float s_pos = (float)(row & (Sq - 1));
        #pragma unroll
        for (int j = 0; j < TNn; j += 4) {
            const int col = block_col + tcol + j;
            float v0 = gelu_exact(acc[i][j+0] + bias[col + 0]);
            float v1 = gelu_exact(acc[i][j+1] + bias[col + 1]);
            float v2 = gelu_exact(acc[i][j+2] + bias[col + 2]);
            float v3 = gelu_exact(acc[i][j+3] + bias[col + 3]);
            float4 o;
            if (do_rope) {
                int hd0 = col & (HDq - 1);
                float th0 = __expf(-((float)hd0 / (float)HDq) * LOG_BASE);
                float sn0, cs0; sincosf(s_pos * th0, &sn0, &cs0);
                o.x = v0 * cs0 - v1 * sn0;
                o.y = v1 * cs0 + v0 * sn0;
                int hd2 = (col + 2) & (HDq - 1);
                float th2 = __expf(-((float)hd2 / (float)HDq) * LOG_BASE);
                float sn2, cs2; sincosf(s_pos * th2, &sn2, &cs2);
                o.z = v2 * cs2 - v3 * sn2;
                o.w = v3 * cs2 + v2 * sn2;
            } else {
                o.x = v0; o.y = v1; o.z = v2; o.w = v3;
            }
            *(float4*)(crow + j) = o;
        }
    }
}

// ---------------- Register-tiled flash attention ------------------------------
// Groups n in [0,32): e = n>>4 (sequence parity), h = n&15 (head).
// Position p in [0,2048): b = p>>10, s = 2*(p&1023) + e.
// Element access: arr[(b*S+s)*D + h*64 + hd].
// CTA: 64 queries x full key sweep, 64 keys per tile, 256 threads, 4x4 microtile.
// ty = tid>>4 -> query group (4 rows), tx = tid&15 -> key group / dim group.
// smem: Qs[d][q], KP (K as [d][k], reused as P[q][k]), Vs[k][d]  = 48KB exactly.
#define ATQ 64
#define ATK 64

__global__ __launch_bounds__(256)
void attn_tiled()
{
    __shared__ float Qs[HDq * ATQ];   // [d][q]
    __shared__ float KP[HDq * ATK];   // [d][k] during S; then P[q][k]
    __shared__ float Vs[ATK * HDq];   // [k][d]

    const int tid = threadIdx.x;
    const int tx = tid & 15;
    const int ty = tid >> 4;
    const int n = blockIdx.y;
    const int e = n >> 4;
    const int h = n & 15;
    const int q0 = blockIdx.x * ATQ;

    // load Q tile transposed: Qs[d][q]
    #pragma unroll
    for (int l = 0; l < 4; l++) {
        int i  = tid + l * 256;           // 0..1023
        int ql = i >> 4;                  // 0..63
        int dc = (i & 15) * 4;            // 0..60
        int p  = q0 + ql;
        int b  = p >> 10;
        int s  = 2 * (p & 1023) + e;
        float4 t = *(const float4*)(g_qp + (size_t)(b * Sq + s) * Dq + h * HDq + dc);
        Qs[(dc + 0) * ATQ + ql] = t.x;
        Qs[(dc + 1) * ATQ + ql] = t.y;
        Qs[(dc + 2) * ATQ + ql] = t.z;
        Qs[(dc + 3) * ATQ + ql] = t.w;
    }

    float m[4], lsum[4], O[4][4];
    #pragma unroll
    for (int i = 0; i < 4; i++) {
        m[i] = -1e30f; lsum[i] = 0.0f;
        #pragma unroll
        for (int j = 0; j < 4; j++) O[i][j] = 0.0f;
    }

    for (int kt = 0; kt < Sq; kt += ATK) {
        __syncthreads();   // prior PV done (first iter: separates Q stores too)

        // load K transposed [d][k] + V natural [k][d]
        #pragma unroll
        for (int l = 0; l < 4; l++) {
            int i  = tid + l * 256;
            int kl = i >> 4;
            int dc = (i & 15) * 4;
            int p  = kt + kl;
            int b  = p >> 10;
            int s  = 2 * (p & 1023) + e;
            size_t off = (size_t)(b * Sq + s) * Dq + h * HDq + dc;
            float4 kv = *(const float4*)(g_kp + off);
            KP[(dc + 0) * ATK + kl] = kv.x;
            KP[(dc + 1) * ATK + kl] = kv.y;
            KP[(dc + 2) * ATK + kl] = kv.z;
            KP[(dc + 3) * ATK + kl] = kv.w;
            float4 vv = *(const float4*)(g_vp + off);
            *(float4*)(&Vs[kl * HDq + dc]) = vv;
        }
        __syncthreads();

        // S = Q @ K^T : 4x4 microtile
        float sc[4][4];
        #pragma unroll
        for (int i = 0; i < 4; i++)
            #pragma unroll
            for (int j = 0; j < 4; j++) sc[i][j] = 0.0f;

        #pragma unroll 16
        for (int kk = 0; kk < HDq; kk++) {
            float4 a = *(const float4*)(&Qs[kk * ATQ + ty * 4]);   // broadcast
            float4 b4 = *(const float4*)(&KP[kk * ATK + tx * 4]);  // contiguous
            float ar[4] = {a.x, a.y, a.z, a.w};
            float br[4] = {b4.x, b4.y, b4.z, b4.w};
            #pragma unroll
            for (int i = 0; i < 4; i++)
                #pragma unroll
                for (int j = 0; j < 4; j++)
                    sc[i][j] = fmaf(ar[i], br[j], sc[i][j]);
        }

        // online softmax per query row (reduce over 16-lane tx group)
        #pragma unroll
        for (int i = 0; i < 4; i++) {
            float s0 = sc[i][0] * SCALE_ATT;
            float s1 = sc[i][1] * SCALE_ATT;
            float s2 = sc[i][2] * SCALE_ATT;
            float s3 = sc[i][3] * SCALE_ATT;
            float tm = fmaxf(fmaxf(s0, s1), fmaxf(s2, s3));
            tm = fmaxf(tm, __shfl_xor_sync(0xffffffffu, tm, 1));
            tm = fmaxf(tm, __shfl_xor_sync(0xffffffffu, tm, 2));
            tm = fmaxf(tm, __shfl_xor_sync(0xffffffffu, tm, 4));
            tm = fmaxf(tm, __shfl_xor_sync(0xffffffffu, tm, 8));
            float mnew = fmaxf(m[i], tm);
            float corr = __expf(m[i] - mnew);
            m[i] = mnew;
            float p0 = __expf(s0 - mnew);
            float p1 = __expf(s1 - mnew);
            float p2 = __expf(s2 - mnew);
            float p3 = __expf(s3 - mnew);
            sc[i][0] = p0; sc[i][1] = p1; sc[i][2] = p2; sc[i][3] = p3;
            float ps = (p0 + p1) + (p2 + p3);
            ps += __shfl_xor_sync(0xffffffffu, ps, 1);
            ps += __shfl_xor_sync(0xffffffffu, ps, 2);
            ps += __shfl_xor_sync(0xffffffffu, ps, 4);
            ps += __shfl_xor_sync(0xffffffffu, ps, 8);
            lsum[i] = lsum[i] * corr + ps;
            #pragma unroll
            for (int j = 0; j < 4; j++) O[i][j] *= corr;
        }

        __syncthreads();   // everyone done reading KP as K

        // write P[q][k] into KP
        #pragma unroll
        for (int i = 0; i < 4; i++) {
            float4 t;
            t.x = sc[i][0]; t.y = sc[i][1]; t.z = sc[i][2]; t.w = sc[i][3];
            *(float4*)(&KP[(ty * 4 + i) * ATK + tx * 4]) = t;
        }
        __syncthreads();

        // O += P @ V : 4x4 microtile (dims = tx*4..)
        #pragma unroll 16
        for (int kk = 0; kk < ATK; kk++) {
            float4 vv = *(const float4*)(&Vs[kk * HDq + tx * 4]);
            float p0 = KP[(ty * 4 + 0) * ATK + kk];
            float p1 = KP[(ty * 4 + 1) * ATK + kk];
            float p2 = KP[(ty * 4 + 2) * ATK + kk];
            float p3 = KP[(ty * 4 + 3) * ATK + kk];
            O[0][0] = fmaf(p0, vv.x, O[0][0]); O[0][1] = fmaf(p0, vv.y, O[0][1]);
            O[0][2] = fmaf(p0, vv.z, O[0][2]); O[0][3] = fmaf(p0, vv.w, O[0][3]);
            O[1][0] = fmaf(p1, vv.x, O[1][0]); O[1][1] = fmaf(p1, vv.y, O[1][1]);
            O[1][2] = fmaf(p1, vv.z, O[1][2]); O[1][3] = fmaf(p1, vv.w, O[1][3]);
            O[2][0] = fmaf(p2, vv.x, O[2][0]); O[2][1] = fmaf(p2, vv.y, O[2][1]);
            O[2][2] = fmaf(p2, vv.z, O[2][2]); O[2][3] = fmaf(p2, vv.w, O[2][3]);
            O[3][0] = fmaf(p3, vv.x, O[3][0]); O[3][1] = fmaf(p3, vv.y, O[3][1]);
            O[3][2] = fmaf(p3, vv.z, O[3][2]); O[3][3] = fmaf(p3, vv.w, O[3][3]);
        }
    }

    // epilogue: normalize + store
    #pragma unroll
    for (int i = 0; i < 4; i++) {
        float inv = 1.0f / lsum[i];
        int p = q0 + ty * 4 + i;
        int b = p >> 10;
        int s = 2 * (p & 1023) + e;
        float4 t;
        t.x = O[i][0] * inv; t.y = O[i][1] * inv;
        t.z = O[i][2] * inv; t.w = O[i][3] * inv;
        *(float4*)(g_att + (size_t)(b * Sq + s) * Dq + h * HDq + tx * 4) = t;
    }
}

// ---------------- launch ------------------------------------------------------
extern "C" void kernel_launch(void* const* d_in, const int* in_sizes, int n_in,
                              void* d_out, int out_size)
{
    const float* q  = (const float*)d_in[0];
    const float* k  = (const float*)d_in[1];
    const float* v  = (const float*)d_in[2];
    const float* Wq = (const float*)d_in[3];
    const float* bq = (const float*)d_in[4];
    const float* Wk = (const float*)d_in[5];
    const float* bk = (const float*)d_in[6];
    const float* Wv = (const float*)d_in[7];
    const float* bv = (const float*)d_in[8];
    const float* Wo = (const float*)d_in[9];
    const float* bo = (const float*)d_in[10];
    float* out = (float*)d_out;

    float *p_qp, *p_kp, *p_vp, *p_att;
    cudaGetSymbolAddress((void**)&p_qp,  g_qp);
    cudaGetSymbolAddress((void**)&p_kp,  g_kp);
    cudaGetSymbolAddress((void**)&p_vp,  g_vp);
    cudaGetSymbolAddress((void**)&p_att, g_att);

    ProjArgs pa;
    pa.A[0] = q;  pa.A[1] = k;  pa.A[2] = v;
    pa.W[0] = Wq; pa.W[1] = Wk; pa.W[2] = Wv;
    pa.bias[0] = bq; pa.bias[1] = bk; pa.bias[2] = bv;
    pa.C[0] = p_qp; pa.C[1] = p_kp; pa.C[2] = p_vp;

    dim3 pgrid(Mq / BM, Dq / BN, 3);   // (32, 8, 3)
    gemm_nt_bias_gelu<true, true><<<pgrid, 256>>>(pa);

    dim3 agrid(Sq / ATQ, 32);          // (32, 32)
    attn_tiled<<<agrid, 256>>>();

    ProjArgs po;
    po.A[0] = p_att; po.W[0] = Wo; po.bias[0] = bo; po.C[0] = out;
    po.A[1] = po.A[2] = nullptr; po.W[1] = po.W[2] = nullptr;
    po.bias[1] = po.bias[2] = nullptr; po.C[1] = po.C[2] = nullptr;

    dim3 ogrid(Mq / BM, Dq / BN, 1);   // (32, 8)
    gemm_nt_bias_gelu<false, false><<<ogrid, 256>>>(po);
}

// round 14
// speedup vs baseline: 1.1006x; 1.0223x over previous
#include <cuda_runtime.h>
#include <cuda_bf16.h>
#include <math.h>

// Problem constants
#define Bq   2
#define Sq   2048
#define Dq   1024
#define Hq   16
#define HDq  64
#define Mq   (Bq*Sq)          // 4096 rows
#define SCALE_ATT 0.03125f    // sqrt(1/1024)

// ---------------- scratch (static device globals; no allocations) -------------
__device__ float g_qp [Mq*Dq];
__device__ float g_kp [Mq*Dq];
__device__ float g_vp [Mq*Dq];
__device__ float g_att[Mq*Dq];

// ---------------- packed f32x2 helpers (sm_103a FFMA2 path) -------------------
__device__ __forceinline__ unsigned long long fma2(unsigned long long a,
                                                   unsigned long long b,
                                                   unsigned long long c) {
    unsigned long long d;
    asm("fma.rn.f32x2 %0, %1, %2, %3;" : "=l"(d) : "l"(a), "l"(b), "l"(c));
    return d;
}
__device__ __forceinline__ unsigned long long pack2(float lo, float hi) {
    unsigned long long d;
    asm("mov.b64 %0, {%1, %2};" : "=l"(d) : "r"(__float_as_uint(lo)), "r"(__float_as_uint(hi)));
    return d;
}
__device__ __forceinline__ unsigned long long dup2(float x) {
    unsigned long long d;
    asm("mov.b64 %0, {%1, %1};" : "=l"(d) : "r"(__float_as_uint(x)));
    return d;
}
__device__ __forceinline__ void unpack2(unsigned long long v, float& lo, float& hi) {
    unsigned int a, b;
    asm("mov.b64 {%0, %1}, %2;" : "=r"(a), "=r"(b) : "l"(v));
    lo = __uint_as_float(a); hi = __uint_as_float(b);
}

// ---------------- GELU (exact, matches jax approximate=False) -----------------
__device__ __forceinline__ float gelu_exact(float x) {
    return 0.5f * x * (1.0f + erff(x * 0.70710678118654752f));
}

// ---------------- GEMM: C[m,n] = post( sum_k A[m,k]*W[n,k] + b[n] ) -----------
// A: [M,K] row-major, W: [N,K] row-major (X @ W^T). M=4096, N=K=1024.
#define BM 128
#define BN 128
#define BKk 16
#define TMm 8
#define TNn 8
#define NT  (Dq / BKk)   // 64 k-tiles

struct ProjArgs {
    const float* A[3];
    const float* W[3];
    const float* bias[3];
    float*       C[3];
};

template <bool FUSED3, bool ROPE>
__global__ __launch_bounds__(256)
void gemm_nt_bias_gelu(ProjArgs pa)
{
    __shared__ float As[2][BKk][BM];
    __shared__ float Bs[2][BKk][BN];

    const int z = FUSED3 ? blockIdx.z : 0;
    const float* __restrict__ A    = pa.A[z];
    const float* __restrict__ W    = pa.W[z];
    const float* __restrict__ bias = pa.bias[z];
    float* __restrict__ C          = pa.C[z];
    const bool do_rope = ROPE && (!FUSED3 || z < 2);

    const int tid = threadIdx.x;
    const int block_row = blockIdx.x * BM;
    const int block_col = blockIdx.y * BN;

    const int trow = (tid >> 4) * TMm;   // 0..120
    const int tcol = (tid & 15) * TNn;   // 0..120

    const int r0  = tid >> 2;            // 0..63
    const int r1  = r0 + 64;             // 64..127
    const int kc  = (tid & 3) * 4;       // 0,4,8,12

    // packed accumulators: acc2[i][jp] = {C[i][2jp], C[i][2jp+1]}
    unsigned long long acc2[TMm][TNn/2];
    #pragma unroll
    for (int i = 0; i < TMm; i++)
        #pragma unroll
        for (int j = 0; j < TNn/2; j++) acc2[i][j] = 0ULL;

    float4 pa0, pa1, pw0, pw1;

    {
        const float* Ab = A + (size_t)block_row * Dq + kc;
        const float* Wb = W + (size_t)block_col * Dq + kc;
        pa0 = *(const float4*)(Ab + (size_t)r0 * Dq);
        pa1 = *(const float4*)(Ab + (size_t)r1 * Dq);
        pw0 = *(const float4*)(Wb + (size_t)r0 * Dq);
        pw1 = *(const float4*)(Wb + (size_t)r1 * Dq);
    }
    As[0][kc+0][r0] = pa0.x; As[0][kc+1][r0] = pa0.y; As[0][kc+2][r0] = pa0.z; As[0][kc+3][r0] = pa0.w;
    As[0][kc+0][r1] = pa1.x; As[0][kc+1][r1] = pa1.y; As[0][kc+2][r1] = pa1.z; As[0][kc+3][r1] = pa1.w;
    Bs[0][kc+0][r0] = pw0.x; Bs[0][kc+1][r0] = pw0.y; Bs[0][kc+2][r0] = pw0.z; Bs[0][kc+3][r0] = pw0.w;
    Bs[0][kc+0][r1] = pw1.x; Bs[0][kc+1][r1] = pw1.y; Bs[0][kc+2][r1] = pw1.z; Bs[0][kc+3][r1] = pw1.w;
    __syncthreads();

    for (int kt = 0; kt < NT; kt++) {
        const int cur = kt & 1;
        const int nxt = cur ^ 1;

        if (kt + 1 < NT) {
            const int k0 = (kt + 1) * BKk;
            const float* Ab = A + (size_t)block_row * Dq + k0 + kc;
            const float* Wb = W + (size_t)block_col * Dq + k0 + kc;
            pa0 = *(const float4*)(Ab + (size_t)r0 * Dq);
            pa1 = *(const float4*)(Ab + (size_t)r1 * Dq);
            pw0 = *(const float4*)(Wb + (size_t)r0 * Dq);
            pw1 = *(const float4*)(Wb + (size_t)r1 * Dq);
        }

        #pragma unroll
        for (int kk = 0; kk < BKk; kk++) {
            // a values (8 floats) then duplicated into f32x2 lanes
            float ar[TMm];
            #pragma unroll
            for (int i = 0; i < TMm; i += 4) {
                float4 t = *(const float4*)(&As[cur][kk][trow + i]);
                ar[i] = t.x; ar[i+1] = t.y; ar[i+2] = t.z; ar[i+3] = t.w;
            }
            // b pairs load directly as packed 64-bit lanes
            ulonglong2 b01 = *(const ulonglong2*)(&Bs[cur][kk][tcol]);
            ulonglong2 b23 = *(const ulonglong2*)(&Bs[cur][kk][tcol + 4]);
            #pragma unroll
            for (int i = 0; i < TMm; i++) {
                unsigned long long ad = dup2(ar[i]);
                acc2[i][0] = fma2(ad, b01.x, acc2[i][0]);
                acc2[i][1] = fma2(ad, b01.y, acc2[i][1]);
                acc2[i][2] = fma2(ad, b23.x, acc2[i][2]);
                acc2[i][3] = fma2(ad, b23.y, acc2[i][3]);
            }
        }

        if (kt + 1 < NT) {
            As[nxt][kc+0][r0] = pa0.x; As[nxt][kc+1][r0] = pa0.y; As[nxt][kc+2][r0] = pa0.z; As[nxt][kc+3][r0] = pa0.w;
            As[nxt][kc+0][r1] = pa1.x; As[nxt][kc+1][r1] = pa1.y; As[nxt][kc+2][r1] = pa1.z; As[nxt][kc+3][r1] = pa1.w;
            Bs[nxt][kc+0][r0] = pw0.x; Bs[nxt][kc+1][r0] = pw0.y; Bs[nxt][kc+2][r0] = pw0.z; Bs[nxt][kc+3][r0] = pw0.w;
            Bs[nxt][kc+0][r1] = pw1.x; Bs[nxt][kc+1][r1] = pw1.y; Bs[nxt][kc+2][r1] = pw1.z; Bs[nxt][kc+3][r1] = pw1.w;
            __syncthreads();
        }
    }

    const float LOG_BASE = 9.210340371976184f; // ln(10000)
    #pragma unroll
    for (int i = 0; i < TMm; i++) {
        const int row = block_row + trow + i;
        float* crow = C + (size_t)row * Dq + block_col + tcol;
        const float s_pos = (float)(row & (Sq - 1));
        float accr[TNn];
        #pragma unroll
        for (int jp = 0; jp < TNn/2; jp++) unpack2(acc2[i][jp], accr[2*jp], accr[2*jp+1]);
        #pragma unroll
        for (int j = 0; j < TNn; j += 4) {
            const int col = block_col + tcol + j;
            float v0 = gelu_exact(accr[j+0] + bias[col + 0]);
            float v1 = gelu_exact(accr[j+1] + bias[col + 1]);
            float v2 = gelu_exact(accr[j+2] + bias[col + 2]);
            float v3 = gelu_exact(accr[j+3] + bias[col + 3]);
            float4 o;
            if (do_rope) {
                int hd0 = col & (HDq - 1);
                float th0 = __expf(-((float)hd0 / (float)HDq) * LOG_BASE);
                float sn0, cs0; sincosf(s_pos * th0, &sn0, &cs0);
                o.x = v0 * cs0 - v1 * sn0;
                o.y = v1 * cs0 + v0 * sn0;
                int hd2 = (col + 2) & (HDq - 1);
                float th2 = __expf(-((float)hd2 / (float)HDq) * LOG_BASE);
                float sn2, cs2; sincosf(s_pos * th2, &sn2, &cs2);
                o.z = v2 * cs2 - v3 * sn2;
                o.w = v3 * cs2 + v2 * sn2;
            } else {
                o.x = v0; o.y = v1; o.z = v2; o.w = v3;
            }
            *(float4*)(crow + j) = o;
        }
    }
}

// ---------------- Register-tiled flash attention (packed f32x2) ---------------
// Groups n in [0,32): e = n>>4 (sequence parity), h = n&15 (head).
// Position p in [0,2048): b = p>>10, s = 2*(p&1023) + e.
// Element access: arr[(b*S+s)*D + h*64 + hd].
#define ATQ 64
#define ATK 64

__global__ __launch_bounds__(256)
void attn_tiled()
{
    __shared__ float Qs[HDq * ATQ];   // [d][q]
    __shared__ float KP[HDq * ATK];   // [d][k] during S; then P[q][k]
    __shared__ float Vs[ATK * HDq];   // [k][d]

    const int tid = threadIdx.x;
    const int tx = tid & 15;
    const int ty = tid >> 4;
    const int n = blockIdx.y;
    const int e = n >> 4;
    const int h = n & 15;
    const int q0 = blockIdx.x * ATQ;

    // load Q tile transposed: Qs[d][q]
    #pragma unroll
    for (int l = 0; l < 4; l++) {
        int i  = tid + l * 256;           // 0..1023
        int ql = i >> 4;                  // 0..63
        int dc = (i & 15) * 4;            // 0..60
        int p  = q0 + ql;
        int b  = p >> 10;
        int s  = 2 * (p & 1023) + e;
        float4 t = *(const float4*)(g_qp + (size_t)(b * Sq + s) * Dq + h * HDq + dc);
        Qs[(dc + 0) * ATQ + ql] = t.x;
        Qs[(dc + 1) * ATQ + ql] = t.y;
        Qs[(dc + 2) * ATQ + ql] = t.z;
        Qs[(dc + 3) * ATQ + ql] = t.w;
    }

    float m[4], lsum[4];
    unsigned long long O2[4][2];       // O packed along d: {d0,d1},{d2,d3}
    #pragma unroll
    for (int i = 0; i < 4; i++) {
        m[i] = -1e30f; lsum[i] = 0.0f;
        O2[i][0] = 0ULL; O2[i][1] = 0ULL;
    }

    for (int kt = 0; kt < Sq; kt += ATK) {
        __syncthreads();   // prior PV done (first iter: separates Q stores too)

        // load K transposed [d][k] + V natural [k][d]
        #pragma unroll
        for (int l = 0; l < 4; l++) {
            int i  = tid + l * 256;
            int kl = i >> 4;
            int dc = (i & 15) * 4;
            int p  = kt + kl;
            int b  = p >> 10;
            int s  = 2 * (p & 1023) + e;
            size_t off = (size_t)(b * Sq + s) * Dq + h * HDq + dc;
            float4 kv = *(const float4*)(g_kp + off);
            KP[(dc + 0) * ATK + kl] = kv.x;
            KP[(dc + 1) * ATK + kl] = kv.y;
            KP[(dc + 2) * ATK + kl] = kv.z;
            KP[(dc + 3) * ATK + kl] = kv.w;
            float4 vv = *(const float4*)(g_vp + off);
            *(float4*)(&Vs[kl * HDq + dc]) = vv;
        }
        __syncthreads();

        // S = Q @ K^T : 4x4 microtile, packed along keys (j)
        unsigned long long sc2[4][2];
        #pragma unroll
        for (int i = 0; i < 4; i++) { sc2[i][0] = 0ULL; sc2[i][1] = 0ULL; }

        #pragma unroll 16
        for (int kk = 0; kk < HDq; kk++) {
            float4 a = *(const float4*)(&Qs[kk * ATQ + ty * 4]);      // broadcast
            ulonglong2 bp = *(const ulonglong2*)(&KP[kk * ATK + tx * 4]); // key pairs
            unsigned long long a0 = dup2(a.x), a1 = dup2(a.y), a2 = dup2(a.z), a3 = dup2(a.w);
            sc2[0][0] = fma2(a0, bp.x, sc2[0][0]); sc2[0][1] = fma2(a0, bp.y, sc2[0][1]);
            sc2[1][0] = fma2(a1, bp.x, sc2[1][0]); sc2[1][1] = fma2(a1, bp.y, sc2[1][1]);
            sc2[2][0] = fma2(a2, bp.x, sc2[2][0]); sc2[2][1] = fma2(a2, bp.y, sc2[2][1]);
            sc2[3][0] = fma2(a3, bp.x, sc2[3][0]); sc2[3][1] = fma2(a3, bp.y, sc2[3][1]);
        }

        // online softmax per query row (reduce over 16-lane tx group)
        float sc[4][4];
        #pragma unroll
        for (int i = 0; i < 4; i++) {
            unpack2(sc2[i][0], sc[i][0], sc[i][1]);
            unpack2(sc2[i][1], sc[i][2], sc[i][3]);
        }
        float corr[4];
        #pragma unroll
        for (int i = 0; i < 4; i++) {
            float s0 = sc[i][0] * SCALE_ATT;
            float s1 = sc[i][1] * SCALE_ATT;
            float s2 = sc[i][2] * SCALE_ATT;
            float s3 = sc[i][3] * SCALE_ATT;
            float tm = fmaxf(fmaxf(s0, s1), fmaxf(s2, s3));
            tm = fmaxf(tm, __shfl_xor_sync(0xffffffffu, tm, 1));
            tm = fmaxf(tm, __shfl_xor_sync(0xffffffffu, tm, 2));
            tm = fmaxf(tm, __shfl_xor_sync(0xffffffffu, tm, 4));
            tm = fmaxf(tm, __shfl_xor_sync(0xffffffffu, tm, 8));
            float mnew = fmaxf(m[i], tm);
            corr[i] = __expf(m[i] - mnew);
            m[i] = mnew;
            float p0 = __expf(s0 - mnew);
            float p1 = __expf(s1 - mnew);
            float p2 = __expf(s2 - mnew);
            float p3 = __expf(s3 - mnew);
            sc[i][0] = p0; sc[i][1] = p1; sc[i][2] = p2; sc[i][3] = p3;
            float ps = (p0 + p1) + (p2 + p3);
            ps += __shfl_xor_sync(0xffffffffu, ps, 1);
            ps += __shfl_xor_sync(0xffffffffu, ps, 2);
            ps += __shfl_xor_sync(0xffffffffu, ps, 4);
            ps += __shfl_xor_sync(0xffffffffu, ps, 8);
            lsum[i] = lsum[i] * corr[i] + ps;
            unsigned long long c2 = dup2(corr[i]);
            unsigned long long z2 = 0ULL;
            O2[i][0] = fma2(O2[i][0], c2, z2);
            O2[i][1] = fma2(O2[i][1], c2, z2);
        }

        __syncthreads();   // everyone done reading KP as K

        // write P[q][k] into KP
        #pragma unroll
        for (int i = 0; i < 4; i++) {
            float4 t;
            t.x = sc[i][0]; t.y = sc[i][1]; t.z = sc[i][2]; t.w = sc[i][3];
            *(float4*)(&KP[(ty * 4 + i) * ATK + tx * 4]) = t;
        }
        __syncthreads();

        // O += P @ V : process keys in blocks of 4, P rows loaded as float4
        #pragma unroll 4
        for (int kb = 0; kb < ATK; kb += 4) {
            float4 pr0 = *(const float4*)(&KP[(ty * 4 + 0) * ATK + kb]);
            float4 pr1 = *(const float4*)(&KP[(ty * 4 + 1) * ATK + kb]);
            float4 pr2 = *(const float4*)(&KP[(ty * 4 + 2) * ATK + kb]);
            float4 pr3 = *(const float4*)(&KP[(ty * 4 + 3) * ATK + kb]);
            const float* p0a = &pr0.x;
            const float* p1a = &pr1.x;
            const float* p2a = &pr2.x;
            const float* p3a = &pr3.x;
            #pragma unroll
            for (int u = 0; u < 4; u++) {
                ulonglong2 vv = *(const ulonglong2*)(&Vs[(kb + u) * HDq + tx * 4]);
                unsigned long long d0 = dup2(p0a[u]);
                unsigned long long d1 = dup2(p1a[u]);
                unsigned long long d2 = dup2(p2a[u]);
                unsigned long long d3 = dup2(p3a[u]);
                O2[0][0] = fma2(d0, vv.x, O2[0][0]); O2[0][1] = fma2(d0, vv.y, O2[0][1]);
                O2[1][0] = fma2(d1, vv.x, O2[1][0]); O2[1][1] = fma2(d1, vv.y, O2[1][1]);
                O2[2][0] = fma2(d2, vv.x, O2[2][0]); O2[2][1] = fma2(d2, vv.y, O2[2][1]);
                O2[3][0] = fma2(d3, vv.x, O2[3][0]); O2[3][1] = fma2(d3, vv.y, O2[3][1]);
            }
        }
    }

    // epilogue: normalize + store
    #pragma unroll
    for (int i = 0; i < 4; i++) {
        float inv = 1.0f / lsum[i];
        int p = q0 + ty * 4 + i;
        int b = p >> 10;
        int s = 2 * (p & 1023) + e;
        float o0, o1, o2, o3;
        unpack2(O2[i][0], o0, o1);
        unpack2(O2[i][1], o2, o3);
        float4 t;
        t.x = o0 * inv; t.y = o1 * inv;
        t.z = o2 * inv; t.w = o3 * inv;
        *(float4*)(g_att + (size_t)(b * Sq + s) * Dq + h * HDq + tx * 4) = t;
    }
}

// ---------------- launch ------------------------------------------------------
extern "C" void kernel_launch(void* const* d_in, const int* in_sizes, int n_in,
                              void* d_out, int out_size)
{
    const float* q  = (const float*)d_in[0];
    const float* k  = (const float*)d_in[1];
    const float* v  = (const float*)d_in[2];
    const float* Wq = (const float*)d_in[3];
    const float* bq = (const float*)d_in[4];
    const float* Wk = (const float*)d_in[5];
    const float* bk = (const float*)d_in[6];
    const float* Wv = (const float*)d_in[7];
    const float* bv = (const float*)d_in[8];
    const float* Wo = (const float*)d_in[9];
    const float* bo = (const float*)d_in[10];
    float* out = (float*)d_out;

    float *p_qp, *p_kp, *p_vp, *p_att;
    cudaGetSymbolAddress((void**)&p_qp,  g_qp);
    cudaGetSymbolAddress((void**)&p_kp,  g_kp);
    cudaGetSymbolAddress((void**)&p_vp,  g_vp);
    cudaGetSymbolAddress((void**)&p_att, g_att);

    ProjArgs pa;
    pa.A[0] = q;  pa.A[1] = k;  pa.A[2] = v;
    pa.W[0] = Wq; pa.W[1] = Wk; pa.W[2] = Wv;
    pa.bias[0] = bq; pa.bias[1] = bk; pa.bias[2] = bv;
    pa.C[0] = p_qp; pa.C[1] = p_kp; pa.C[2] = p_vp;

    dim3 pgrid(Mq / BM, Dq / BN, 3);   // (32, 8, 3)
    gemm_nt_bias_gelu<true, true><<<pgrid, 256>>>(pa);

    dim3 agrid(Sq / ATQ, 32);          // (32, 32)
    attn_tiled<<<agrid, 256>>>();

    ProjArgs po;
    po.A[0] = p_att; po.W[0] = Wo; po.bias[0] = bo; po.C[0] = out;
    po.A[1] = po.A[2] = nullptr; po.W[1] = po.W[2] = nullptr;
    po.bias[1] = po.bias[2] = nullptr; po.C[1] = po.C[2] = nullptr;

    dim3 ogrid(Mq / BM, Dq / BN, 1);   // (32, 8)
    gemm_nt_bias_gelu<false, false><<<ogrid, 256>>>(po);
}